// round 5
// baseline (speedup 1.0000x reference)
#include <cuda_runtime.h>
#include <cstdint>
#include <cstddef>

#define B4    4
#define NSEQ  4096
#define CDIM  1024
#define NH    16
#define HD    64
#define NBH   (B4*NH)
#define KVSPLIT 8

// Scratch (allowed: __device__ globals, no runtime allocation)
static __device__ float g_q  [NBH * NSEQ * HD];   // [B,H,N,D]
static __device__ float g_k  [NBH * NSEQ * HD];
static __device__ float g_v  [NBH * NSEQ * HD];
static __device__ float g_kv [NBH * HD * HD];     // [B,H,D,D]
static __device__ float g_kvp[KVSPLIT * NBH * HD * HD];
static __device__ float g_o  [B4 * NSEQ * CDIM];  // [B,N,C]

__device__ __forceinline__ float tf32r(float x) {
    uint32_t u;
    asm("cvt.rna.tf32.f32 %0, %1;" : "=r"(u) : "f"(x));
    return __uint_as_float(u);
}

__device__ __forceinline__ void mma8(float c[4], const float a[4], const float b[2]) {
    const uint32_t* A  = reinterpret_cast<const uint32_t*>(a);
    const uint32_t* Bv = reinterpret_cast<const uint32_t*>(b);
    asm volatile(
        "mma.sync.aligned.m16n8k8.row.col.f32.tf32.tf32.f32 "
        "{%0,%1,%2,%3}, {%4,%5,%6,%7}, {%8,%9}, {%0,%1,%2,%3};\n"
        : "+f"(c[0]), "+f"(c[1]), "+f"(c[2]), "+f"(c[3])
        : "r"(A[0]), "r"(A[1]), "r"(A[2]), "r"(A[3]),
          "r"(Bv[0]), "r"(Bv[1]));
}

// ---------------------------------------------------------------------------
// C[m,o] = sum_k X[m,k] * W[o,k]   (X: [16384,1024] row-major, W: [1024,1024])
// MODE 0: scatter result into qkv buffer (sel picks q/k/v) in [B,H,N,D] layout.
// MODE 1: X is g_o, writes outp[m*CDIM+o] + bias[o].
// Tile: BM=128, BN=128, BK=16. 8 warps (2x4), warp tile 64x32, m16n8k8 tf32.
// GRID: blockIdx.x = n-tile (FAST) so all n-CTAs of one m-strip run together
//       -> X strip read once from DRAM, reused 8x via L2; W fully L2-resident.
// ---------------------------------------------------------------------------
template<int MODE>
__global__ __launch_bounds__(256, 1)
void proj_kernel(const float* __restrict__ X, const float* __restrict__ W,
                 const float* __restrict__ bias, float* __restrict__ outp, int sel)
{
    __shared__ float sA[2][16][136];   // [k][m], pad 8 -> conflict-free frag reads
    __shared__ float sB[2][16][136];   // [k][n]

    const int tid    = threadIdx.x;
    const int lane   = tid & 31;
    const int warpId = tid >> 5;
    const int g  = lane >> 2;
    const int t  = lane & 3;
    const int wm = warpId & 1;   // 2 warps over M
    const int wn = warpId >> 1;  // 4 warps over N
    const int n0 = blockIdx.x * 128;   // FAST dim = output columns
    const int m0 = blockIdx.y * 128;   // SLOW dim = row strip

    const int lrow = tid >> 2;        // 0..63 (and +64)
    const int lkc  = (tid & 3) * 4;   // 0,4,8,12

    const float* Xs = (MODE == 1) ? (const float*)g_o : X;
    const float* pa0 = Xs + (size_t)(m0 + lrow) * CDIM + lkc;
    const float* pb0 = W  + (size_t)(n0 + lrow) * CDIM + lkc;

    float4 rA0, rA1, rB0, rB1;

    float acc[4][4][4];
#pragma unroll
    for (int a = 0; a < 4; ++a)
#pragma unroll
        for (int b = 0; b < 4; ++b)
#pragma unroll
            for (int c = 0; c < 4; ++c) acc[a][b][c] = 0.f;

    auto fetch = [&](int kt) {
        const float* pa = pa0 + kt * 16;
        const float* pb = pb0 + kt * 16;
        rA0 = *reinterpret_cast<const float4*>(pa);
        rA1 = *reinterpret_cast<const float4*>(pa + 64 * CDIM);
        rB0 = *reinterpret_cast<const float4*>(pb);
        rB1 = *reinterpret_cast<const float4*>(pb + 64 * CDIM);
    };
    auto stage = [&](int bf) {
        sA[bf][lkc+0][lrow]    = tf32r(rA0.x);
        sA[bf][lkc+1][lrow]    = tf32r(rA0.y);
        sA[bf][lkc+2][lrow]    = tf32r(rA0.z);
        sA[bf][lkc+3][lrow]    = tf32r(rA0.w);
        sA[bf][lkc+0][lrow+64] = tf32r(rA1.x);
        sA[bf][lkc+1][lrow+64] = tf32r(rA1.y);
        sA[bf][lkc+2][lrow+64] = tf32r(rA1.z);
        sA[bf][lkc+3][lrow+64] = tf32r(rA1.w);
        sB[bf][lkc+0][lrow]    = tf32r(rB0.x);
        sB[bf][lkc+1][lrow]    = tf32r(rB0.y);
        sB[bf][lkc+2][lrow]    = tf32r(rB0.z);
        sB[bf][lkc+3][lrow]    = tf32r(rB0.w);
        sB[bf][lkc+0][lrow+64] = tf32r(rB1.x);
        sB[bf][lkc+1][lrow+64] = tf32r(rB1.y);
        sB[bf][lkc+2][lrow+64] = tf32r(rB1.z);
        sB[bf][lkc+3][lrow+64] = tf32r(rB1.w);
    };

    fetch(0); stage(0); __syncthreads();
    int buf = 0;
    for (int kt = 0; kt < 64; ++kt) {
        if (kt < 63) fetch(kt + 1);
#pragma unroll
        for (int ks = 0; ks < 2; ++ks) {
            const int kk = ks * 8;
            float af[4][4], bfr[4][2];
#pragma unroll
            for (int mi = 0; mi < 4; ++mi) {
                const int rm = wm * 64 + mi * 16 + g;
                af[mi][0] = sA[buf][kk + t][rm];
                af[mi][1] = sA[buf][kk + t][rm + 8];
                af[mi][2] = sA[buf][kk + t + 4][rm];
                af[mi][3] = sA[buf][kk + t + 4][rm + 8];
            }
#pragma unroll
            for (int ni = 0; ni < 4; ++ni) {
                const int cn = wn * 32 + ni * 8 + g;
                bfr[ni][0] = sB[buf][kk + t][cn];
                bfr[ni][1] = sB[buf][kk + t + 4][cn];
            }
#pragma unroll
            for (int mi = 0; mi < 4; ++mi)
#pragma unroll
                for (int ni = 0; ni < 4; ++ni)
                    mma8(acc[mi][ni], af[mi], bfr[ni]);
        }
        if (kt < 63) { stage(buf ^ 1); __syncthreads(); buf ^= 1; }
    }

    float* qkv = nullptr;
    if (MODE == 0) qkv = (sel == 0) ? g_q : (sel == 1) ? g_k : g_v;

#pragma unroll
    for (int mi = 0; mi < 4; ++mi) {
#pragma unroll
        for (int ni = 0; ni < 4; ++ni) {
            const int row = m0 + wm * 64 + mi * 16 + g;
            const int col = n0 + wn * 32 + ni * 8 + 2 * t;
            if (MODE == 0) {
                const int b = row >> 12, n = row & (NSEQ - 1);
                const int h = col >> 6,  d = col & (HD - 1);
                float* p = qkv + (((size_t)(b * NH + h) * NSEQ + n) * HD + d);
                *reinterpret_cast<float2*>(p) =
                    make_float2(acc[mi][ni][0], acc[mi][ni][1]);
                *reinterpret_cast<float2*>(p + 8 * HD) =
                    make_float2(acc[mi][ni][2], acc[mi][ni][3]);
            } else {
                const float b0v = bias[col], b1v = bias[col + 1];
                *reinterpret_cast<float2*>(outp + (size_t)row * CDIM + col) =
                    make_float2(acc[mi][ni][0] + b0v, acc[mi][ni][1] + b1v);
                *reinterpret_cast<float2*>(outp + (size_t)(row + 8) * CDIM + col) =
                    make_float2(acc[mi][ni][2] + b0v, acc[mi][ni][3] + b1v);
            }
        }
    }
}

// ---------------------------------------------------------------------------
// kv partial: kvp[split][bh][d][e] = sum_{n in split} k[bh][n][d]*v[bh][n][e]
// grid (NBH, KVSPLIT); each split covers 16 tiles of 32 rows.
// ---------------------------------------------------------------------------
__global__ __launch_bounds__(256, 1)
void kv_partial()
{
    __shared__ float sk[2][32][72];
    __shared__ float sv[2][32][72];
    const int bh = blockIdx.x;
    const int split = blockIdx.y;
    const int nt0 = split * 16;
    const float* Kp = g_k + (size_t)bh * NSEQ * HD;
    const float* Vp = g_v + (size_t)bh * NSEQ * HD;

    const int tid = threadIdx.x;
    const int lane = tid & 31, warpId = tid >> 5;
    const int g = lane >> 2, t = lane & 3;
    const int wm = warpId & 1, wn = warpId >> 1;
    const int lrow = tid >> 4;
    const int lc   = (tid & 15) * 4;

    float4 rk0, rk1, rv0, rv1;
    auto fetch = [&](int nt) {
        const size_t base = (size_t)(nt * 32 + lrow) * HD + lc;
        rk0 = *reinterpret_cast<const float4*>(Kp + base);
        rk1 = *reinterpret_cast<const float4*>(Kp + base + 16 * HD);
        rv0 = *reinterpret_cast<const float4*>(Vp + base);
        rv1 = *reinterpret_cast<const float4*>(Vp + base + 16 * HD);
    };
    auto cvt4 = [](float4 v) {
        return make_float4(tf32r(v.x), tf32r(v.y), tf32r(v.z), tf32r(v.w));
    };
    auto stage = [&](int bf) {
        *reinterpret_cast<float4*>(&sk[bf][lrow][lc])      = cvt4(rk0);
        *reinterpret_cast<float4*>(&sk[bf][lrow + 16][lc]) = cvt4(rk1);
        *reinterpret_cast<float4*>(&sv[bf][lrow][lc])      = cvt4(rv0);
        *reinterpret_cast<float4*>(&sv[bf][lrow + 16][lc]) = cvt4(rv1);
    };

    float acc[2][2][4];
#pragma unroll
    for (int a = 0; a < 2; ++a)
#pragma unroll
        for (int b = 0; b < 2; ++b)
#pragma unroll
            for (int c = 0; c < 4; ++c) acc[a][b][c] = 0.f;

    fetch(nt0); stage(0); __syncthreads();
    int buf = 0;
    for (int it = 0; it < 16; ++it) {
        if (it < 15) fetch(nt0 + it + 1);
#pragma unroll
        for (int ks = 0; ks < 4; ++ks) {
            const int kk = ks * 8;
            float af[2][4], bfr[2][2];
#pragma unroll
            for (int mi = 0; mi < 2; ++mi) {
                const int rd = wm * 32 + mi * 16 + g;
                af[mi][0] = sk[buf][kk + t][rd];
                af[mi][1] = sk[buf][kk + t][rd + 8];
                af[mi][2] = sk[buf][kk + t + 4][rd];
                af[mi][3] = sk[buf][kk + t + 4][rd + 8];
            }
#pragma unroll
            for (int ni = 0; ni < 2; ++ni) {
                const int ce = wn * 16 + ni * 8 + g;
                bfr[ni][0] = sv[buf][kk + t][ce];
                bfr[ni][1] = sv[buf][kk + t + 4][ce];
            }
#pragma unroll
            for (int mi = 0; mi < 2; ++mi)
#pragma unroll
                for (int ni = 0; ni < 2; ++ni)
                    mma8(acc[mi][ni], af[mi], bfr[ni]);
        }
        if (it < 15) { stage(buf ^ 1); __syncthreads(); buf ^= 1; }
    }

    float* O = g_kvp + ((size_t)split * NBH + bh) * HD * HD;
#pragma unroll
    for (int mi = 0; mi < 2; ++mi)
#pragma unroll
        for (int ni = 0; ni < 2; ++ni) {
            const int d0 = wm * 32 + mi * 16 + g;
            const int e  = wn * 16 + ni * 8 + 2 * t;
            *reinterpret_cast<float2*>(O + (size_t)d0 * HD + e) =
                make_float2(acc[mi][ni][0], acc[mi][ni][1]);
            *reinterpret_cast<float2*>(O + (size_t)(d0 + 8) * HD + e) =
                make_float2(acc[mi][ni][2], acc[mi][ni][3]);
        }
}

__global__ __launch_bounds__(256, 1)
void kv_reduce()
{
    const int i = blockIdx.x * 256 + threadIdx.x;   // float4 index
    float4 s = make_float4(0.f, 0.f, 0.f, 0.f);
#pragma unroll
    for (int sp = 0; sp < KVSPLIT; ++sp) {
        float4 v = *reinterpret_cast<const float4*>(g_kvp + (size_t)sp * NBH * HD * HD + i * 4);
        s.x += v.x; s.y += v.y; s.z += v.z; s.w += v.w;
    }
    *reinterpret_cast<float4*>(g_kv + (size_t)i * 4) =
        make_float4(s.x * 0.125f, s.y * 0.125f, s.z * 0.125f, s.w * 0.125f);
}

// ---------------------------------------------------------------------------
// attn: out[bh][n][e] = sum_d q[bh][n][d] * kv[bh][d][e]  -> g_o [B,N,C]
// ---------------------------------------------------------------------------
__global__ __launch_bounds__(256, 1)
void attn_kernel()
{
    __shared__ float sq [64][68];
    __shared__ float skv[64][72];
    const int bh = blockIdx.y;
    const int n0 = blockIdx.x * 64;
    const float* Qp  = g_q  + (size_t)bh * NSEQ * HD + (size_t)n0 * HD;
    const float* KVp = g_kv + (size_t)bh * HD * HD;

    const int tid = threadIdx.x;
    const int lane = tid & 31, warpId = tid >> 5;
    const int g = lane >> 2, t = lane & 3;
    const int wm = warpId & 1, wn = warpId >> 1;
    const int lrow = tid >> 4;
    const int lc   = (tid & 15) * 4;

#pragma unroll
    for (int i = 0; i < 4; ++i) {
        const int r = lrow + i * 16;
        float4 a = *reinterpret_cast<const float4*>(Qp + (size_t)r * HD + lc);
        *reinterpret_cast<float4*>(&sq[r][lc]) =
            make_float4(tf32r(a.x), tf32r(a.y), tf32r(a.z), tf32r(a.w));
        float4 b = *reinterpret_cast<const float4*>(KVp + (size_t)r * HD + lc);
        *reinterpret_cast<float4*>(&skv[r][lc]) =
            make_float4(tf32r(b.x), tf32r(b.y), tf32r(b.z), tf32r(b.w));
    }
    __syncthreads();

    float acc[2][2][4];
#pragma unroll
    for (int a = 0; a < 2; ++a)
#pragma unroll
        for (int b = 0; b < 2; ++b)
#pragma unroll
            for (int c = 0; c < 4; ++c) acc[a][b][c] = 0.f;

#pragma unroll
    for (int ks = 0; ks < 8; ++ks) {
        const int kk = ks * 8;
        float af[2][4], bfr[2][2];
#pragma unroll
        for (int mi = 0; mi < 2; ++mi) {
            const int rn = wm * 32 + mi * 16 + g;
            af[mi][0] = sq[rn][kk + t];
            af[mi][1] = sq[rn + 8][kk + t];
            af[mi][2] = sq[rn][kk + t + 4];
            af[mi][3] = sq[rn + 8][kk + t + 4];
        }
#pragma unroll
        for (int ni = 0; ni < 2; ++ni) {
            const int ce = wn * 16 + ni * 8 + g;
            bfr[ni][0] = skv[kk + t][ce];
            bfr[ni][1] = skv[kk + t + 4][ce];
        }
#pragma unroll
        for (int mi = 0; mi < 2; ++mi)
#pragma unroll
            for (int ni = 0; ni < 2; ++ni)
                mma8(acc[mi][ni], af[mi], bfr[ni]);
    }

    const int b = bh >> 4, h = bh & (NH - 1);
#pragma unroll
    for (int mi = 0; mi < 2; ++mi)
#pragma unroll
        for (int ni = 0; ni < 2; ++ni) {
            const int nn = n0 + wm * 32 + mi * 16 + g;
            const int e  = wn * 16 + ni * 8 + 2 * t;
            float* p = g_o + ((size_t)(b * NSEQ + nn)) * CDIM + h * HD + e;
            *reinterpret_cast<float2*>(p) =
                make_float2(acc[mi][ni][0], acc[mi][ni][1]);
            *reinterpret_cast<float2*>(p + (size_t)8 * CDIM) =
                make_float2(acc[mi][ni][2], acc[mi][ni][3]);
        }
}

extern "C" void kernel_launch(void* const* d_in, const int* in_sizes, int n_in,
                              void* d_out, int out_size)
{
    (void)in_sizes; (void)n_in; (void)out_size;
    const float* x  = (const float*)d_in[0];
    const float* Wq = (const float*)d_in[1];
    const float* Wk = (const float*)d_in[2];
    const float* Wv = (const float*)d_in[3];
    const float* Wo = (const float*)d_in[4];
    const float* bo = (const float*)d_in[5];
    float* out = (float*)d_out;

    // x = n-tiles (fast), y = m-strips (slow): X strip hits L2, W stays resident
    dim3 gproj(CDIM / 128, (B4 * NSEQ) / 128);   // (8, 128)
    proj_kernel<0><<<gproj, 256>>>(x, Wq, nullptr, nullptr, 0);
    proj_kernel<0><<<gproj, 256>>>(x, Wk, nullptr, nullptr, 1);
    proj_kernel<0><<<gproj, 256>>>(x, Wv, nullptr, nullptr, 2);
    kv_partial<<<dim3(NBH, KVSPLIT), 256>>>();
    kv_reduce<<<(NBH * HD * HD / 4) / 256, 256>>>();
    attn_kernel<<<dim3(NSEQ / 64, NBH), 256>>>();
    proj_kernel<1><<<gproj, 256>>>(nullptr, Wo, bo, out, 0);
}

// round 6
// speedup vs baseline: 1.4540x; 1.4540x over previous
#include <cuda_runtime.h>
#include <cstdint>
#include <cstddef>

#define B4    4
#define NSEQ  4096
#define CDIM  1024
#define NH    16
#define HD    64
#define NBH   (B4*NH)
#define KVSPLIT 8

// Scratch (allowed: __device__ globals, no runtime allocation)
static __device__ float g_x  [B4 * NSEQ * CDIM];  // tf32-rounded X
static __device__ float g_wq [CDIM * CDIM];       // tf32-rounded weights
static __device__ float g_wk [CDIM * CDIM];
static __device__ float g_wv [CDIM * CDIM];
static __device__ float g_wo [CDIM * CDIM];
static __device__ float g_q  [NBH * NSEQ * HD];   // [B,H,N,D]
static __device__ float g_k  [NBH * NSEQ * HD];
static __device__ float g_v  [NBH * NSEQ * HD];
static __device__ float g_kv [NBH * HD * HD];     // [B,H,D,D]
static __device__ float g_kvp[KVSPLIT * NBH * HD * HD];
static __device__ float g_o  [B4 * NSEQ * CDIM];  // [B,N,C], tf32-rounded

__device__ __forceinline__ float tf32r(float x) {
    uint32_t u;
    asm("cvt.rna.tf32.f32 %0, %1;" : "=r"(u) : "f"(x));
    return __uint_as_float(u);
}

__device__ __forceinline__ uint32_t smem_u32(const void* p) {
    uint32_t a;
    asm("{ .reg .u64 t; cvta.to.shared.u64 t, %1; cvt.u32.u64 %0, t; }"
        : "=r"(a) : "l"(p));
    return a;
}

#define CP16(saddr, gptr) \
    asm volatile("cp.async.cg.shared.global [%0], [%1], 16;" :: "r"(saddr), "l"(gptr))
#define CP_COMMIT()  asm volatile("cp.async.commit_group;")
#define CP_WAIT1()   asm volatile("cp.async.wait_group 1;")
#define CP_WAIT0()   asm volatile("cp.async.wait_group 0;")

__device__ __forceinline__ void mma8(float c[4], const float a[4], const float b[2]) {
    const uint32_t* A  = reinterpret_cast<const uint32_t*>(a);
    const uint32_t* Bv = reinterpret_cast<const uint32_t*>(b);
    asm volatile(
        "mma.sync.aligned.m16n8k8.row.col.f32.tf32.tf32.f32 "
        "{%0,%1,%2,%3}, {%4,%5,%6,%7}, {%8,%9}, {%0,%1,%2,%3};\n"
        : "+f"(c[0]), "+f"(c[1]), "+f"(c[2]), "+f"(c[3])
        : "r"(A[0]), "r"(A[1]), "r"(A[2]), "r"(A[3]),
          "r"(Bv[0]), "r"(Bv[1]));
}

// ---------------------------------------------------------------------------
// pre-pass: tf32-round a tensor into a device-global copy (which selects dst)
// ---------------------------------------------------------------------------
__global__ __launch_bounds__(256, 1)
void round_tf32(const float* __restrict__ src, int which)
{
    float* dst = (which == 0) ? g_x
               : (which == 1) ? g_wq
               : (which == 2) ? g_wk
               : (which == 3) ? g_wv : g_wo;
    const int i = blockIdx.x * 256 + threadIdx.x;
    float4 v = reinterpret_cast<const float4*>(src)[i];
    reinterpret_cast<float4*>(dst)[i] =
        make_float4(tf32r(v.x), tf32r(v.y), tf32r(v.z), tf32r(v.w));
}

// ---------------------------------------------------------------------------
// proj2: C[m,n] = sum_k A[m,k] * W[n,k], A/W pre-rounded tf32 in device globals.
// MODE 0: A=g_x, W by blockIdx.z in {g_wq,g_wk,g_wv}, scatter into q/k/v [B,H,N,D].
// MODE 1: A=g_o (tf32-rounded by attn), W=g_wo, out = outp + bias.
// 128x128 tile, BK=16, 2-stage cp.async double buffer, 8 warps (2x4), 64x32/warp.
// smem [row][k] stride 20 -> conflict-free frag LDS; 2 CTAs/SM guaranteed.
// ---------------------------------------------------------------------------
template<int MODE>
__global__ __launch_bounds__(256, 2)
void proj2(const float* __restrict__ bias, float* __restrict__ outp)
{
    __shared__ float sA[2][128][20];
    __shared__ float sB[2][128][20];

    const int tid  = threadIdx.x;
    const int lane = tid & 31, warpId = tid >> 5;
    const int g  = lane >> 2, t = lane & 3;
    const int wm = warpId & 1, wn = warpId >> 1;
    const int n0 = blockIdx.x * 128;
    const int m0 = blockIdx.y * 128;
    const int z  = blockIdx.z;

    const float* A = (MODE == 0) ? (const float*)g_x : (const float*)g_o;
    const float* W = (MODE == 0)
        ? ((z == 0) ? (const float*)g_wq : (z == 1) ? (const float*)g_wk : (const float*)g_wv)
        : (const float*)g_wo;

    // loader: row = tid>>1 (0..127), word offset in row = (tid&1)*8 (+{0,4})
    const int lr  = tid >> 1;
    const int lco = (tid & 1) * 8;
    const float* gA = A + (size_t)(m0 + lr) * CDIM + lco;
    const float* gB = W + (size_t)(n0 + lr) * CDIM + lco;
    const uint32_t saA = smem_u32(&sA[0][lr][lco]);
    const uint32_t saB = smem_u32(&sB[0][lr][lco]);
    const uint32_t STG = 128 * 20 * 4;   // bytes per stage

    auto load_stage = [&](int s, int kt) {
        const float* pa = gA + kt * 16;
        const float* pb = gB + kt * 16;
        const uint32_t oa = saA + (uint32_t)s * STG;
        const uint32_t ob = saB + (uint32_t)s * STG;
        CP16(oa,      pa);
        CP16(oa + 16, pa + 4);
        CP16(ob,      pb);
        CP16(ob + 16, pb + 4);
        CP_COMMIT();
    };

    float acc[4][4][4];
#pragma unroll
    for (int a = 0; a < 4; ++a)
#pragma unroll
        for (int b = 0; b < 4; ++b)
#pragma unroll
            for (int c = 0; c < 4; ++c) acc[a][b][c] = 0.f;

    load_stage(0, 0);
    for (int kt = 0; kt < 64; ++kt) {
        const int cur = kt & 1;
        if (kt < 63) load_stage(cur ^ 1, kt + 1);
        if (kt < 63) CP_WAIT1(); else CP_WAIT0();
        __syncthreads();

#pragma unroll
        for (int ks = 0; ks < 2; ++ks) {
            const int kk = ks * 8;
            float af[4][4], bfr[4][2];
#pragma unroll
            for (int mi = 0; mi < 4; ++mi) {
                const int rm = wm * 64 + mi * 16 + g;
                af[mi][0] = sA[cur][rm][kk + t];
                af[mi][1] = sA[cur][rm + 8][kk + t];
                af[mi][2] = sA[cur][rm][kk + t + 4];
                af[mi][3] = sA[cur][rm + 8][kk + t + 4];
            }
#pragma unroll
            for (int ni = 0; ni < 4; ++ni) {
                const int cn = wn * 32 + ni * 8 + g;
                bfr[ni][0] = sB[cur][cn][kk + t];
                bfr[ni][1] = sB[cur][cn][kk + t + 4];
            }
#pragma unroll
            for (int mi = 0; mi < 4; ++mi)
#pragma unroll
                for (int ni = 0; ni < 4; ++ni)
                    mma8(acc[mi][ni], af[mi], bfr[ni]);
        }
        __syncthreads();   // reads of 'cur' done before it is refilled at kt+2
    }

    float* qkv = nullptr;
    if (MODE == 0) qkv = (z == 0) ? g_q : (z == 1) ? g_k : g_v;

#pragma unroll
    for (int mi = 0; mi < 4; ++mi) {
#pragma unroll
        for (int ni = 0; ni < 4; ++ni) {
            const int row = m0 + wm * 64 + mi * 16 + g;
            const int col = n0 + wn * 32 + ni * 8 + 2 * t;
            if (MODE == 0) {
                const int b = row >> 12, n = row & (NSEQ - 1);
                const int h = col >> 6,  d = col & (HD - 1);
                float* p = qkv + (((size_t)(b * NH + h) * NSEQ + n) * HD + d);
                *reinterpret_cast<float2*>(p) =
                    make_float2(acc[mi][ni][0], acc[mi][ni][1]);
                *reinterpret_cast<float2*>(p + 8 * HD) =
                    make_float2(acc[mi][ni][2], acc[mi][ni][3]);
            } else {
                const float b0v = bias[col], b1v = bias[col + 1];
                *reinterpret_cast<float2*>(outp + (size_t)row * CDIM + col) =
                    make_float2(acc[mi][ni][0] + b0v, acc[mi][ni][1] + b1v);
                *reinterpret_cast<float2*>(outp + (size_t)(row + 8) * CDIM + col) =
                    make_float2(acc[mi][ni][2] + b0v, acc[mi][ni][3] + b1v);
            }
        }
    }
}

// ---------------------------------------------------------------------------
// kv partial: kvp[split][bh][d][e] = sum_{n in split} k[bh][n][d]*v[bh][n][e]
// ---------------------------------------------------------------------------
__global__ __launch_bounds__(256, 1)
void kv_partial()
{
    __shared__ float sk[2][32][72];
    __shared__ float sv[2][32][72];
    const int bh = blockIdx.x;
    const int split = blockIdx.y;
    const int nt0 = split * 16;
    const float* Kp = g_k + (size_t)bh * NSEQ * HD;
    const float* Vp = g_v + (size_t)bh * NSEQ * HD;

    const int tid = threadIdx.x;
    const int lane = tid & 31, warpId = tid >> 5;
    const int g = lane >> 2, t = lane & 3;
    const int wm = warpId & 1, wn = warpId >> 1;
    const int lrow = tid >> 4;
    const int lc   = (tid & 15) * 4;

    float4 rk0, rk1, rv0, rv1;
    auto fetch = [&](int nt) {
        const size_t base = (size_t)(nt * 32 + lrow) * HD + lc;
        rk0 = *reinterpret_cast<const float4*>(Kp + base);
        rk1 = *reinterpret_cast<const float4*>(Kp + base + 16 * HD);
        rv0 = *reinterpret_cast<const float4*>(Vp + base);
        rv1 = *reinterpret_cast<const float4*>(Vp + base + 16 * HD);
    };
    auto cvt4 = [](float4 v) {
        return make_float4(tf32r(v.x), tf32r(v.y), tf32r(v.z), tf32r(v.w));
    };
    auto stage = [&](int bf) {
        *reinterpret_cast<float4*>(&sk[bf][lrow][lc])      = cvt4(rk0);
        *reinterpret_cast<float4*>(&sk[bf][lrow + 16][lc]) = cvt4(rk1);
        *reinterpret_cast<float4*>(&sv[bf][lrow][lc])      = cvt4(rv0);
        *reinterpret_cast<float4*>(&sv[bf][lrow + 16][lc]) = cvt4(rv1);
    };

    float acc[2][2][4];
#pragma unroll
    for (int a = 0; a < 2; ++a)
#pragma unroll
        for (int b = 0; b < 2; ++b)
#pragma unroll
            for (int c = 0; c < 4; ++c) acc[a][b][c] = 0.f;

    fetch(nt0); stage(0); __syncthreads();
    int buf = 0;
    for (int it = 0; it < 16; ++it) {
        if (it < 15) fetch(nt0 + it + 1);
#pragma unroll
        for (int ks = 0; ks < 4; ++ks) {
            const int kk = ks * 8;
            float af[2][4], bfr[2][2];
#pragma unroll
            for (int mi = 0; mi < 2; ++mi) {
                const int rd = wm * 32 + mi * 16 + g;
                af[mi][0] = sk[buf][kk + t][rd];
                af[mi][1] = sk[buf][kk + t][rd + 8];
                af[mi][2] = sk[buf][kk + t + 4][rd];
                af[mi][3] = sk[buf][kk + t + 4][rd + 8];
            }
#pragma unroll
            for (int ni = 0; ni < 2; ++ni) {
                const int ce = wn * 16 + ni * 8 + g;
                bfr[ni][0] = sv[buf][kk + t][ce];
                bfr[ni][1] = sv[buf][kk + t + 4][ce];
            }
#pragma unroll
            for (int mi = 0; mi < 2; ++mi)
#pragma unroll
                for (int ni = 0; ni < 2; ++ni)
                    mma8(acc[mi][ni], af[mi], bfr[ni]);
        }
        if (it < 15) { stage(buf ^ 1); __syncthreads(); buf ^= 1; }
    }

    float* O = g_kvp + ((size_t)split * NBH + bh) * HD * HD;
#pragma unroll
    for (int mi = 0; mi < 2; ++mi)
#pragma unroll
        for (int ni = 0; ni < 2; ++ni) {
            const int d0 = wm * 32 + mi * 16 + g;
            const int e  = wn * 16 + ni * 8 + 2 * t;
            *reinterpret_cast<float2*>(O + (size_t)d0 * HD + e) =
                make_float2(acc[mi][ni][0], acc[mi][ni][1]);
            *reinterpret_cast<float2*>(O + (size_t)(d0 + 8) * HD + e) =
                make_float2(acc[mi][ni][2], acc[mi][ni][3]);
        }
}

__global__ __launch_bounds__(256, 1)
void kv_reduce()
{
    const int i = blockIdx.x * 256 + threadIdx.x;   // float4 index
    float4 s = make_float4(0.f, 0.f, 0.f, 0.f);
#pragma unroll
    for (int sp = 0; sp < KVSPLIT; ++sp) {
        float4 v = *reinterpret_cast<const float4*>(g_kvp + (size_t)sp * NBH * HD * HD + i * 4);
        s.x += v.x; s.y += v.y; s.z += v.z; s.w += v.w;
    }
    *reinterpret_cast<float4*>(g_kv + (size_t)i * 4) =
        make_float4(s.x * 0.125f, s.y * 0.125f, s.z * 0.125f, s.w * 0.125f);
}

// ---------------------------------------------------------------------------
// attn: out[bh][n][e] = sum_d q[bh][n][d] * kv[bh][d][e]  -> g_o [B,N,C]
// writes tf32-ROUNDED values (g_o only feeds the final projection).
// ---------------------------------------------------------------------------
__global__ __launch_bounds__(256, 1)
void attn_kernel()
{
    __shared__ float sq [64][68];
    __shared__ float skv[64][72];
    const int bh = blockIdx.y;
    const int n0 = blockIdx.x * 64;
    const float* Qp  = g_q  + (size_t)bh * NSEQ * HD + (size_t)n0 * HD;
    const float* KVp = g_kv + (size_t)bh * HD * HD;

    const int tid = threadIdx.x;
    const int lane = tid & 31, warpId = tid >> 5;
    const int g = lane >> 2, t = lane & 3;
    const int wm = warpId & 1, wn = warpId >> 1;
    const int lrow = tid >> 4;
    const int lc   = (tid & 15) * 4;

#pragma unroll
    for (int i = 0; i < 4; ++i) {
        const int r = lrow + i * 16;
        float4 a = *reinterpret_cast<const float4*>(Qp + (size_t)r * HD + lc);
        *reinterpret_cast<float4*>(&sq[r][lc]) =
            make_float4(tf32r(a.x), tf32r(a.y), tf32r(a.z), tf32r(a.w));
        float4 b = *reinterpret_cast<const float4*>(KVp + (size_t)r * HD + lc);
        *reinterpret_cast<float4*>(&skv[r][lc]) =
            make_float4(tf32r(b.x), tf32r(b.y), tf32r(b.z), tf32r(b.w));
    }
    __syncthreads();

    float acc[2][2][4];
#pragma unroll
    for (int a = 0; a < 2; ++a)
#pragma unroll
        for (int b = 0; b < 2; ++b)
#pragma unroll
            for (int c = 0; c < 4; ++c) acc[a][b][c] = 0.f;

#pragma unroll
    for (int ks = 0; ks < 8; ++ks) {
        const int kk = ks * 8;
        float af[2][4], bfr[2][2];
#pragma unroll
        for (int mi = 0; mi < 2; ++mi) {
            const int rn = wm * 32 + mi * 16 + g;
            af[mi][0] = sq[rn][kk + t];
            af[mi][1] = sq[rn + 8][kk + t];
            af[mi][2] = sq[rn][kk + t + 4];
            af[mi][3] = sq[rn + 8][kk + t + 4];
        }
#pragma unroll
        for (int ni = 0; ni < 2; ++ni) {
            const int ce = wn * 16 + ni * 8 + g;
            bfr[ni][0] = skv[kk + t][ce];
            bfr[ni][1] = skv[kk + t + 4][ce];
        }
#pragma unroll
        for (int mi = 0; mi < 2; ++mi)
#pragma unroll
            for (int ni = 0; ni < 2; ++ni)
                mma8(acc[mi][ni], af[mi], bfr[ni]);
    }

    const int b = bh >> 4, h = bh & (NH - 1);
#pragma unroll
    for (int mi = 0; mi < 2; ++mi)
#pragma unroll
        for (int ni = 0; ni < 2; ++ni) {
            const int nn = n0 + wm * 32 + mi * 16 + g;
            const int e  = wn * 16 + ni * 8 + 2 * t;
            float* p = g_o + ((size_t)(b * NSEQ + nn)) * CDIM + h * HD + e;
            *reinterpret_cast<float2*>(p) =
                make_float2(tf32r(acc[mi][ni][0]), tf32r(acc[mi][ni][1]));
            *reinterpret_cast<float2*>(p + (size_t)8 * CDIM) =
                make_float2(tf32r(acc[mi][ni][2]), tf32r(acc[mi][ni][3]));
        }
}

extern "C" void kernel_launch(void* const* d_in, const int* in_sizes, int n_in,
                              void* d_out, int out_size)
{
    (void)in_sizes; (void)n_in; (void)out_size;
    const float* x  = (const float*)d_in[0];
    const float* Wq = (const float*)d_in[1];
    const float* Wk = (const float*)d_in[2];
    const float* Wv = (const float*)d_in[3];
    const float* Wo = (const float*)d_in[4];
    const float* bo = (const float*)d_in[5];
    float* out = (float*)d_out;

    // pre-pass: tf32-round X and weights once
    round_tf32<<<(B4 * NSEQ * CDIM / 4) / 256, 256>>>(x, 0);     // 16384 blocks
    round_tf32<<<(CDIM * CDIM / 4) / 256, 256>>>(Wq, 1);         // 1024 blocks
    round_tf32<<<(CDIM * CDIM / 4) / 256, 256>>>(Wk, 2);
    round_tf32<<<(CDIM * CDIM / 4) / 256, 256>>>(Wv, 3);
    round_tf32<<<(CDIM * CDIM / 4) / 256, 256>>>(Wo, 4);

    // fused q,k,v projections (z picks weight + destination)
    proj2<0><<<dim3(CDIM / 128, (B4 * NSEQ) / 128, 3), 256>>>(nullptr, nullptr);
    kv_partial<<<dim3(NBH, KVSPLIT), 256>>>();
    kv_reduce<<<(NBH * HD * HD / 4) / 256, 256>>>();
    attn_kernel<<<dim3(NSEQ / 64, NBH), 256>>>();
    proj2<1><<<dim3(CDIM / 128, (B4 * NSEQ) / 128, 1), 256>>>(bo, out);
}

// round 13
// speedup vs baseline: 1.6152x; 1.1108x over previous
#include <cuda_runtime.h>
#include <cstdint>
#include <cstddef>

#define B4    4
#define NSEQ  4096
#define CDIM  1024
#define NH    16
#define HD    64
#define NBH   (B4*NH)
#define KVSPLIT 8

// device-global scratch (no runtime allocation)
static __device__ float g_x  [B4 * NSEQ * CDIM];   // tf32-rounded X
static __device__ float g_wk [CDIM * CDIM];        // tf32-rounded Wk
static __device__ float g_wv [CDIM * CDIM];        // tf32-rounded Wv
static __device__ float g_wo [CDIM * CDIM];        // tf32-rounded Wo
static __device__ float g_k  [NBH * NSEQ * HD];    // [B,H,N,D]
static __device__ float g_v  [NBH * NSEQ * HD];
static __device__ float g_kv [NBH * HD * HD];      // fp32, scaled
static __device__ float g_kvp[KVSPLIT * NBH * HD * HD];
static __device__ float g_r  [B4 * CDIM * CDIM];   // R[c][he], tf32-rounded
static __device__ float g_gt [B4 * CDIM * CDIM];   // Gt[co][c], tf32-rounded

__device__ __forceinline__ float tf32r(float x) {
    uint32_t u;
    asm("cvt.rna.tf32.f32 %0, %1;" : "=r"(u) : "f"(x));
    return __uint_as_float(u);
}
__device__ __forceinline__ uint32_t smem_u32(const void* p) {
    uint32_t a;
    asm("{ .reg .u64 t; cvta.to.shared.u64 t, %1; cvt.u32.u64 %0, t; }"
        : "=r"(a) : "l"(p));
    return a;
}
#define CP16(saddr, gptr) \
    asm volatile("cp.async.cg.shared.global [%0], [%1], 16;" :: "r"(saddr), "l"(gptr))
#define CP_COMMIT()  asm volatile("cp.async.commit_group;")
#define CP_WAIT1()   asm volatile("cp.async.wait_group 1;")
#define CP_WAIT0()   asm volatile("cp.async.wait_group 0;")

__device__ __forceinline__ void mma8(float c[4], const float a[4], const float b[2]) {
    const uint32_t* A  = reinterpret_cast<const uint32_t*>(a);
    const uint32_t* Bv = reinterpret_cast<const uint32_t*>(b);
    asm volatile(
        "mma.sync.aligned.m16n8k8.row.col.f32.tf32.tf32.f32 "
        "{%0,%1,%2,%3}, {%4,%5,%6,%7}, {%8,%9}, {%0,%1,%2,%3};\n"
        : "+f"(c[0]), "+f"(c[1]), "+f"(c[2]), "+f"(c[3])
        : "r"(A[0]), "r"(A[1]), "r"(A[2]), "r"(A[3]),
          "r"(Bv[0]), "r"(Bv[1]));
}

// ---------------------------------------------------------------------------
// prepass: tf32-round into device-global copies (R6-proven body)
// ---------------------------------------------------------------------------
__global__ __launch_bounds__(256, 1)
void round_tf32(const float* __restrict__ src, int which)
{
    float* dst = (which == 0) ? g_x
               : (which == 1) ? g_wk
               : (which == 2) ? g_wv : g_wo;
    const int i = blockIdx.x * 256 + threadIdx.x;
    float4 v = reinterpret_cast<const float4*>(src)[i];
    reinterpret_cast<float4*>(dst)[i] =
        make_float4(tf32r(v.x), tf32r(v.y), tf32r(v.z), tf32r(v.w));
}

// ---------------------------------------------------------------------------
// proj_kv: K/V projections (R6-proven proj2 MODE0 body; z selects Wk/Wv).
// C[m,n] = sum_k X[m,k]*W[n,k], scattered into g_k/g_v [B,H,N,D].
// grid (8, 128, 2), 256 threads, (256,2).
// ---------------------------------------------------------------------------
__global__ __launch_bounds__(256, 2)
void proj_kv()
{
    __shared__ float sA[2][128][20];
    __shared__ float sB[2][128][20];

    const int tid  = threadIdx.x;
    const int lane = tid & 31, warpId = tid >> 5;
    const int g  = lane >> 2, t = lane & 3;
    const int wm = warpId & 1, wn = warpId >> 1;
    const int n0 = blockIdx.x * 128;
    const int m0 = blockIdx.y * 128;
    const int z  = blockIdx.z;

    const float* A = (const float*)g_x;
    const float* W = (z == 0) ? (const float*)g_wk : (const float*)g_wv;

    const int lr  = tid >> 1;
    const int lco = (tid & 1) * 8;
    const float* gA = A + (size_t)(m0 + lr) * CDIM + lco;
    const float* gB = W + (size_t)(n0 + lr) * CDIM + lco;
    const uint32_t saA = smem_u32(&sA[0][lr][lco]);
    const uint32_t saB = smem_u32(&sB[0][lr][lco]);
    const uint32_t STG = 128 * 20 * 4;

    auto load_stage = [&](int s, int kt) {
        const float* pa = gA + kt * 16;
        const float* pb = gB + kt * 16;
        const uint32_t oa = saA + (uint32_t)s * STG;
        const uint32_t ob = saB + (uint32_t)s * STG;
        CP16(oa,      pa);
        CP16(oa + 16, pa + 4);
        CP16(ob,      pb);
        CP16(ob + 16, pb + 4);
        CP_COMMIT();
    };

    float acc[4][4][4];
#pragma unroll
    for (int a = 0; a < 4; ++a)
#pragma unroll
        for (int b = 0; b < 4; ++b)
#pragma unroll
            for (int c = 0; c < 4; ++c) acc[a][b][c] = 0.f;

    load_stage(0, 0);
    for (int kt = 0; kt < 64; ++kt) {
        const int cur = kt & 1;
        if (kt < 63) load_stage(cur ^ 1, kt + 1);
        if (kt < 63) CP_WAIT1(); else CP_WAIT0();
        __syncthreads();
#pragma unroll
        for (int ks = 0; ks < 2; ++ks) {
            const int kk = ks * 8;
            float af[4][4], bfr[4][2];
#pragma unroll
            for (int mi = 0; mi < 4; ++mi) {
                const int rm = wm * 64 + mi * 16 + g;
                af[mi][0] = sA[cur][rm][kk + t];
                af[mi][1] = sA[cur][rm + 8][kk + t];
                af[mi][2] = sA[cur][rm][kk + t + 4];
                af[mi][3] = sA[cur][rm + 8][kk + t + 4];
            }
#pragma unroll
            for (int ni = 0; ni < 4; ++ni) {
                const int cn = wn * 32 + ni * 8 + g;
                bfr[ni][0] = sB[cur][cn][kk + t];
                bfr[ni][1] = sB[cur][cn][kk + t + 4];
            }
#pragma unroll
            for (int mi = 0; mi < 4; ++mi)
#pragma unroll
                for (int ni = 0; ni < 4; ++ni)
                    mma8(acc[mi][ni], af[mi], bfr[ni]);
        }
        __syncthreads();
    }

    float* qkv = (z == 0) ? g_k : g_v;

#pragma unroll
    for (int mi = 0; mi < 4; ++mi) {
#pragma unroll
        for (int ni = 0; ni < 4; ++ni) {
            const int row = m0 + wm * 64 + mi * 16 + g;
            const int col = n0 + wn * 32 + ni * 8 + 2 * t;
            const int b = row >> 12, n = row & (NSEQ - 1);
            const int h = col >> 6,  d = col & (HD - 1);
            float* p = qkv + (((size_t)(b * NH + h) * NSEQ + n) * HD + d);
            *reinterpret_cast<float2*>(p) =
                make_float2(acc[mi][ni][0], acc[mi][ni][1]);
            *reinterpret_cast<float2*>(p + 8 * HD) =
                make_float2(acc[mi][ni][2], acc[mi][ni][3]);
        }
    }
}

// ---------------------------------------------------------------------------
// kv partial (R6-proven): kvp[split][bh] = sum_{n in split} k[n,d]*v[n,e]
// ---------------------------------------------------------------------------
__global__ __launch_bounds__(256, 1)
void kv_partial()
{
    __shared__ float sk[2][32][72];
    __shared__ float sv[2][32][72];
    const int bh = blockIdx.x;
    const int split = blockIdx.y;
    const int nt0 = split * 16;
    const float* Kp = g_k + (size_t)bh * NSEQ * HD;
    const float* Vp = g_v + (size_t)bh * NSEQ * HD;

    const int tid = threadIdx.x;
    const int lane = tid & 31, warpId = tid >> 5;
    const int g = lane >> 2, t = lane & 3;
    const int wm = warpId & 1, wn = warpId >> 1;
    const int lrow = tid >> 4;
    const int lc   = (tid & 15) * 4;

    float4 rk0, rk1, rv0, rv1;
    auto fetch = [&](int nt) {
        const size_t base = (size_t)(nt * 32 + lrow) * HD + lc;
        rk0 = *reinterpret_cast<const float4*>(Kp + base);
        rk1 = *reinterpret_cast<const float4*>(Kp + base + 16 * HD);
        rv0 = *reinterpret_cast<const float4*>(Vp + base);
        rv1 = *reinterpret_cast<const float4*>(Vp + base + 16 * HD);
    };
    auto cvt4 = [](float4 v) {
        return make_float4(tf32r(v.x), tf32r(v.y), tf32r(v.z), tf32r(v.w));
    };
    auto stage = [&](int bf) {
        *reinterpret_cast<float4*>(&sk[bf][lrow][lc])      = cvt4(rk0);
        *reinterpret_cast<float4*>(&sk[bf][lrow + 16][lc]) = cvt4(rk1);
        *reinterpret_cast<float4*>(&sv[bf][lrow][lc])      = cvt4(rv0);
        *reinterpret_cast<float4*>(&sv[bf][lrow + 16][lc]) = cvt4(rv1);
    };

    float acc[2][2][4];
#pragma unroll
    for (int a = 0; a < 2; ++a)
#pragma unroll
        for (int b = 0; b < 2; ++b)
#pragma unroll
            for (int c = 0; c < 4; ++c) acc[a][b][c] = 0.f;

    fetch(nt0); stage(0); __syncthreads();
    int buf = 0;
    for (int it = 0; it < 16; ++it) {
        if (it < 15) fetch(nt0 + it + 1);
#pragma unroll
        for (int ks = 0; ks < 4; ++ks) {
            const int kk = ks * 8;
            float af[2][4], bfr[2][2];
#pragma unroll
            for (int mi = 0; mi < 2; ++mi) {
                const int rd = wm * 32 + mi * 16 + g;
                af[mi][0] = sk[buf][kk + t][rd];
                af[mi][1] = sk[buf][kk + t][rd + 8];
                af[mi][2] = sk[buf][kk + t + 4][rd];
                af[mi][3] = sk[buf][kk + t + 4][rd + 8];
            }
#pragma unroll
            for (int ni = 0; ni < 2; ++ni) {
                const int ce = wn * 16 + ni * 8 + g;
                bfr[ni][0] = sv[buf][kk + t][ce];
                bfr[ni][1] = sv[buf][kk + t + 4][ce];
            }
#pragma unroll
            for (int mi = 0; mi < 2; ++mi)
#pragma unroll
                for (int ni = 0; ni < 2; ++ni)
                    mma8(acc[mi][ni], af[mi], bfr[ni]);
        }
        if (it < 15) { stage(buf ^ 1); __syncthreads(); buf ^= 1; }
    }

    float* O = g_kvp + ((size_t)split * NBH + bh) * HD * HD;
#pragma unroll
    for (int mi = 0; mi < 2; ++mi)
#pragma unroll
        for (int ni = 0; ni < 2; ++ni) {
            const int d0 = wm * 32 + mi * 16 + g;
            const int e  = wn * 16 + ni * 8 + 2 * t;
            *reinterpret_cast<float2*>(O + (size_t)d0 * HD + e) =
                make_float2(acc[mi][ni][0], acc[mi][ni][1]);
            *reinterpret_cast<float2*>(O + (size_t)(d0 + 8) * HD + e) =
                make_float2(acc[mi][ni][2], acc[mi][ni][3]);
        }
}

__global__ __launch_bounds__(256, 1)
void kv_reduce()
{
    const int i = blockIdx.x * 256 + threadIdx.x;   // float4 index
    float4 s = make_float4(0.f, 0.f, 0.f, 0.f);
#pragma unroll
    for (int sp = 0; sp < KVSPLIT; ++sp) {
        float4 v = *reinterpret_cast<const float4*>(g_kvp + (size_t)sp * NBH * HD * HD + i * 4);
        s.x += v.x; s.y += v.y; s.z += v.z; s.w += v.w;
    }
    *reinterpret_cast<float4*>(g_kv + (size_t)i * 4) =
        make_float4(s.x * 0.125f, s.y * 0.125f, s.z * 0.125f, s.w * 0.125f);
}

// ---------------------------------------------------------------------------
// r_build (scalar SIMT, spill-proof: one scalar accumulator, no arrays):
// R_b[c, h*64+e] = sum_d Wq[h*64+d, c] * kv_bh[d, e]  (Wq exact fp32)
// grid (256 c-chunks of 4, 16 h, 4 b), 256 threads: thread = (cl 0..3, e 0..63)
// ---------------------------------------------------------------------------
__global__ __launch_bounds__(256, 1)
void r_build(const float* __restrict__ Wq)
{
    __shared__ float skv[64][64];
    __shared__ float swq[4][64];
    const int b  = blockIdx.z, h = blockIdx.y;
    const int c0 = blockIdx.x * 4;
    const int tid = threadIdx.x;
    const int cl = tid >> 6;        // 0..3
    const int e  = tid & 63;        // 0..63

    const float* KV = g_kv + (size_t)(b * NH + h) * HD * HD;
    for (int i = tid; i < 4096; i += 256)
        skv[i >> 6][i & 63] = KV[i];
    // swq[cl][d] = Wq[(h*64+d)*CDIM + c0+cl]
    swq[cl][e] = Wq[(size_t)(h * 64 + e) * CDIM + c0 + cl];
    __syncthreads();

    float acc = 0.f;
    for (int d = 0; d < 64; ++d)
        acc += swq[cl][d] * skv[d][e];

    g_r[(size_t)b * CDIM * CDIM + (size_t)(c0 + cl) * CDIM + h * 64 + e] = tf32r(acc);
}

// ---------------------------------------------------------------------------
// gemm_b: R6-proven proj2 body, compile-time K=1024 and strides; per-b pointers
// via compile-time-selected globals (same ternary pattern R6 proved).
// MODE 0: Gt_b[co][c] = sum_he Wo[co,he]*R_b[c,he], tf32-rounded. grid (8,8,4)
// MODE 1: out_b[n][co] = sum_c X_b[n,c]*Gt_b[co,c] + bo[co].       grid (8,32,4)
// ---------------------------------------------------------------------------
template<int MODE>
__global__ __launch_bounds__(256, 2)
void gemm_b(const float* __restrict__ bias, float* __restrict__ outp)
{
    __shared__ float sA[2][128][20];
    __shared__ float sB[2][128][20];

    const int tid  = threadIdx.x;
    const int lane = tid & 31, warpId = tid >> 5;
    const int g  = lane >> 2, t = lane & 3;
    const int wm = warpId & 1, wn = warpId >> 1;
    const int n0 = blockIdx.x * 128;
    const int m0 = blockIdx.y * 128;
    const int z  = blockIdx.z;

    const size_t M1c = (size_t)CDIM * CDIM;
    const size_t MXc = (size_t)NSEQ * CDIM;

    const float* A = (MODE == 0) ? (const float*)g_wo
                                 : (const float*)g_x + (size_t)z * MXc;
    const float* B = (MODE == 0) ? (const float*)g_r  + (size_t)z * M1c
                                 : (const float*)g_gt + (size_t)z * M1c;
    float*       C = (MODE == 0) ? (float*)g_gt + (size_t)z * M1c
                                 : outp + (size_t)z * MXc;

    const int lr  = tid >> 1;
    const int lco = (tid & 1) * 8;
    const float* gA = A + (size_t)(m0 + lr) * CDIM + lco;
    const float* gB = B + (size_t)(n0 + lr) * CDIM + lco;
    const uint32_t saA = smem_u32(&sA[0][lr][lco]);
    const uint32_t saB = smem_u32(&sB[0][lr][lco]);
    const uint32_t STG = 128 * 20 * 4;

    auto load_stage = [&](int s, int kt) {
        const float* pa = gA + kt * 16;
        const float* pb = gB + kt * 16;
        const uint32_t oa = saA + (uint32_t)s * STG;
        const uint32_t ob = saB + (uint32_t)s * STG;
        CP16(oa,      pa);
        CP16(oa + 16, pa + 4);
        CP16(ob,      pb);
        CP16(ob + 16, pb + 4);
        CP_COMMIT();
    };

    float acc[4][4][4];
#pragma unroll
    for (int a = 0; a < 4; ++a)
#pragma unroll
        for (int b = 0; b < 4; ++b)
#pragma unroll
            for (int c = 0; c < 4; ++c) acc[a][b][c] = 0.f;

    load_stage(0, 0);
    for (int kt = 0; kt < 64; ++kt) {
        const int cur = kt & 1;
        if (kt < 63) load_stage(cur ^ 1, kt + 1);
        if (kt < 63) CP_WAIT1(); else CP_WAIT0();
        __syncthreads();
#pragma unroll
        for (int ks = 0; ks < 2; ++ks) {
            const int kk = ks * 8;
            float af[4][4], bfr[4][2];
#pragma unroll
            for (int mi = 0; mi < 4; ++mi) {
                const int rm = wm * 64 + mi * 16 + g;
                af[mi][0] = sA[cur][rm][kk + t];
                af[mi][1] = sA[cur][rm + 8][kk + t];
                af[mi][2] = sA[cur][rm][kk + t + 4];
                af[mi][3] = sA[cur][rm + 8][kk + t + 4];
            }
#pragma unroll
            for (int ni = 0; ni < 4; ++ni) {
                const int cn = wn * 32 + ni * 8 + g;
                bfr[ni][0] = sB[cur][cn][kk + t];
                bfr[ni][1] = sB[cur][cn][kk + t + 4];
            }
#pragma unroll
            for (int mi = 0; mi < 4; ++mi)
#pragma unroll
                for (int ni = 0; ni < 4; ++ni)
                    mma8(acc[mi][ni], af[mi], bfr[ni]);
        }
        __syncthreads();
    }

#pragma unroll
    for (int mi = 0; mi < 4; ++mi) {
#pragma unroll
        for (int ni = 0; ni < 4; ++ni) {
            const int row = m0 + wm * 64 + mi * 16 + g;
            const int col = n0 + wn * 32 + ni * 8 + 2 * t;
            float* p0 = C + (size_t)row * CDIM + col;
            float* p1 = C + (size_t)(row + 8) * CDIM + col;
            if (MODE == 0) {
                *reinterpret_cast<float2*>(p0) =
                    make_float2(tf32r(acc[mi][ni][0]), tf32r(acc[mi][ni][1]));
                *reinterpret_cast<float2*>(p1) =
                    make_float2(tf32r(acc[mi][ni][2]), tf32r(acc[mi][ni][3]));
            } else {
                const float b0v = bias[col], b1v = bias[col + 1];
                *reinterpret_cast<float2*>(p0) =
                    make_float2(acc[mi][ni][0] + b0v, acc[mi][ni][1] + b1v);
                *reinterpret_cast<float2*>(p1) =
                    make_float2(acc[mi][ni][2] + b0v, acc[mi][ni][3] + b1v);
            }
        }
    }
}

extern "C" void kernel_launch(void* const* d_in, const int* in_sizes, int n_in,
                              void* d_out, int out_size)
{
    (void)in_sizes; (void)n_in; (void)out_size;
    const float* x  = (const float*)d_in[0];
    const float* Wq = (const float*)d_in[1];
    const float* Wk = (const float*)d_in[2];
    const float* Wv = (const float*)d_in[3];
    const float* Wo = (const float*)d_in[4];
    const float* bo = (const float*)d_in[5];
    float* out = (float*)d_out;

    // prepass: tf32-round X, Wk, Wv, Wo (Wq stays exact fp32 for r_build)
    round_tf32<<<(B4 * NSEQ * CDIM / 4) / 256, 256>>>(x, 0);
    round_tf32<<<(CDIM * CDIM / 4) / 256, 256>>>(Wk, 1);
    round_tf32<<<(CDIM * CDIM / 4) / 256, 256>>>(Wv, 2);
    round_tf32<<<(CDIM * CDIM / 4) / 256, 256>>>(Wo, 3);

    // K and V projections (R6-proven body)
    proj_kv<<<dim3(CDIM / 128, (B4 * NSEQ) / 128, 2), 256>>>();

    // kv = 0.125 * k^T v per (b,h)  (R6-proven split-8 + reduce)
    kv_partial<<<dim3(NBH, KVSPLIT), 256>>>();
    kv_reduce<<<(NBH * HD * HD / 4) / 256, 256>>>();

    // R_b[c,he] = sum_d Wq[hd,c]*kv[d,e]  (exact fp32, rounded store)
    r_build<<<dim3(256, NH, B4), 256>>>(Wq);

    // Gt_b = Wo (contract he) R_b^T ; then out = X Gt^T + bo
    gemm_b<0><<<dim3(8, 8, B4), 256>>>(nullptr, nullptr);
    gemm_b<1><<<dim3(8, 32, B4), 256>>>(bo, out);
}